// round 1
// baseline (speedup 1.0000x reference)
#include <cuda_runtime.h>
#include <math.h>

#define N_NODES 50000
#define N_EDGES 800000
#define H 64
#define S 16
#define EF 16
#define ATT_W 144   // hidden width of attention MLP
#define UPD_W 128

// ---------------- scratch (static device allocations) ----------------
__device__ float g_Psrc[N_NODES * ATT_W];   // 28.8 MB
__device__ float g_Pdst[N_NODES * ATT_W];   // 28.8 MB
__device__ float g_raw[N_EDGES];            // 3.2 MB
__device__ float g_agg[N_NODES * H];        // 12.8 MB
__device__ int   g_deg[N_NODES];
__device__ int   g_rowptr[N_NODES + 1];
__device__ int   g_cursor[N_NODES];
__device__ int   g_esorted[N_EDGES];        // 3.2 MB

// ---------------- CSR build ----------------
__global__ void zero_kernel() {
    int i = blockIdx.x * blockDim.x + threadIdx.x;
    if (i < N_NODES) { g_deg[i] = 0; g_cursor[i] = 0; }
}

__global__ void hist_kernel(const int* __restrict__ ei) {
    int e = blockIdx.x * blockDim.x + threadIdx.x;
    if (e < N_EDGES) atomicAdd(&g_deg[ei[N_EDGES + e]], 1);
}

// single-block scan over 50k degrees
__global__ void scan_kernel() {
    __shared__ int sums[1024];
    const int CH = (N_NODES + 1023) / 1024;   // 49
    int t = threadIdx.x;
    int begin = t * CH;
    int end = min(begin + CH, N_NODES);
    int s = 0;
    for (int i = begin; i < end; i++) s += g_deg[i];
    sums[t] = s;
    __syncthreads();
    for (int off = 1; off < 1024; off <<= 1) {
        int v = (t >= off) ? sums[t - off] : 0;
        __syncthreads();
        sums[t] += v;
        __syncthreads();
    }
    int run = (t == 0) ? 0 : sums[t - 1];
    for (int i = begin; i < end; i++) { g_rowptr[i] = run; run += g_deg[i]; }
    if (t == 1023) g_rowptr[N_NODES] = sums[1023];
}

__global__ void fill_kernel(const int* __restrict__ ei) {
    int e = blockIdx.x * blockDim.x + threadIdx.x;
    if (e < N_EDGES) {
        int d = ei[N_EDGES + e];
        int pos = atomicAdd(&g_cursor[d], 1);
        g_esorted[g_rowptr[d] + pos] = e;
    }
}

// ---------------- node projections: Psrc/Pdst = [x|x_s] @ W^T ----------------
// block: 160 threads (144 active j-lanes). chunk of 8 nodes.
// smem: Wa[144*81], Wb[144*81] (pad 81 -> conflict-free), Xs[8*80]
__global__ void proj_kernel(const float* __restrict__ x,
                            const float* __restrict__ xs,
                            const float* __restrict__ w1) {
    extern __shared__ float sm[];
    float* Wa = sm;                 // Psrc weights, [j][f] stride 81
    float* Wb = Wa + 144 * 81;      // Pdst weights
    float* Xs = Wb + 144 * 81;      // [8][80]
    int tid = threadIdx.x, nthr = blockDim.x;

    for (int idx = tid; idx < 144 * 80; idx += nthr) {
        int j = idx / 80, f = idx % 80;
        float a, b;
        if (f < 64) { a = w1[j * 176 + f];              b = w1[j * 176 + 64 + f]; }
        else        { a = w1[j * 176 + 128 + (f - 64)]; b = w1[j * 176 + 144 + (f - 64)]; }
        Wa[j * 81 + f] = a;
        Wb[j * 81 + f] = b;
    }
    __syncthreads();

    int nchunks = (N_NODES + 7) / 8;
    for (int c = blockIdx.x; c < nchunks; c += gridDim.x) {
        int n0 = c * 8;
        for (int idx = tid; idx < 8 * 80; idx += nthr) {
            int n = idx / 80, f = idx % 80;
            int node = n0 + n;
            float v = 0.f;
            if (node < N_NODES) v = (f < 64) ? x[node * 64 + f] : xs[node * 16 + (f - 64)];
            Xs[idx] = v;
        }
        __syncthreads();
        if (tid < 144) {
            int j = tid;
            float accA[8], accB[8];
#pragma unroll
            for (int n = 0; n < 8; n++) { accA[n] = 0.f; accB[n] = 0.f; }
            for (int f = 0; f < 80; f++) {
                float wa = Wa[j * 81 + f];
                float wb = Wb[j * 81 + f];
#pragma unroll
                for (int n = 0; n < 8; n++) {
                    float xv = Xs[n * 80 + f];
                    accA[n] = fmaf(wa, xv, accA[n]);
                    accB[n] = fmaf(wb, xv, accB[n]);
                }
            }
#pragma unroll
            for (int n = 0; n < 8; n++) {
                int node = n0 + n;
                if (node < N_NODES) {
                    g_Psrc[node * 144 + j] = accA[n];
                    g_Pdst[node * 144 + j] = accB[n];
                }
            }
        }
        __syncthreads();
    }
}

// ---------------- fused edge attention: raw score per edge ----------------
// warp per edge: h = relu(Psrc[s] + Pdst[d] + ef@We^T + b1); raw = leaky(h.w2 + b2)
__global__ void edge_kernel(const int* __restrict__ ei,
                            const float* __restrict__ ef,
                            const float* __restrict__ w1,
                            const float* __restrict__ b1,
                            const float* __restrict__ w2,
                            const float* __restrict__ b2) {
    __shared__ float Wef[16 * 144];   // [f][j]
    __shared__ float b1s[144], w2s[144];
    __shared__ float b2s;
    int tid = threadIdx.x;
    for (int idx = tid; idx < 16 * 144; idx += blockDim.x) {
        int f = idx / 144, j = idx % 144;
        Wef[idx] = w1[j * 176 + 160 + f];
    }
    if (tid < 144) { b1s[tid] = b1[tid]; w2s[tid] = w2[tid]; }
    if (tid == 0) b2s = b2[0];
    __syncthreads();

    int lane = tid & 31;
    int gw = (blockIdx.x * blockDim.x + tid) >> 5;
    int nw = (gridDim.x * blockDim.x) >> 5;

    for (int e = gw; e < N_EDGES; e += nw) {
        int s = ei[e];
        int d = ei[N_EDGES + e];
        float efv = (lane < 16) ? ef[e * 16 + lane] : 0.f;
        float acc[5];
#pragma unroll
        for (int k = 0; k < 5; k++) {
            int j = lane + 32 * k;
            acc[k] = (j < 144) ? (b1s[j] + g_Psrc[s * 144 + j] + g_Pdst[d * 144 + j]) : 0.f;
        }
#pragma unroll
        for (int f = 0; f < 16; f++) {
            float v = __shfl_sync(0xffffffffu, efv, f);
            const float* wr = &Wef[f * 144];
#pragma unroll
            for (int k = 0; k < 5; k++) {
                int j = lane + 32 * k;
                if (j < 144) acc[k] = fmaf(v, wr[j], acc[k]);
            }
        }
        float p = 0.f;
#pragma unroll
        for (int k = 0; k < 5; k++) {
            int j = lane + 32 * k;
            if (j < 144) p += fmaxf(acc[k], 0.f) * w2s[j];
        }
#pragma unroll
        for (int o = 16; o; o >>= 1) p += __shfl_xor_sync(0xffffffffu, p, o);
        if (lane == 0) {
            float r = p + b2s;
            r = (r > 0.f) ? r : 0.01f * r;   // leaky_relu (slope 0.01)
            g_raw[e] = r;
        }
    }
}

// ---------------- fused segment softmax + weighted aggregation ----------------
// warp per destination node
__global__ void softagg_kernel(const int* __restrict__ ei,
                               const float* __restrict__ x) {
    int warp = (blockIdx.x * blockDim.x + threadIdx.x) >> 5;
    int lane = threadIdx.x & 31;
    if (warp >= N_NODES) return;
    int start = g_rowptr[warp];
    int deg = g_rowptr[warp + 1] - start;

    float m = -1e30f;
    for (int i = lane; i < deg; i += 32) m = fmaxf(m, g_raw[g_esorted[start + i]]);
#pragma unroll
    for (int o = 16; o; o >>= 1) m = fmaxf(m, __shfl_xor_sync(0xffffffffu, m, o));

    float acc0 = 0.f, acc1 = 0.f, ws = 0.f;
    for (int base = 0; base < deg; base += 32) {
        int i = base + lane;
        int e = (i < deg) ? g_esorted[start + i] : 0;
        float w = (i < deg) ? expf(g_raw[e] - m) : 0.f;
        int sv = (i < deg) ? ei[e] : 0;
        ws += w;
        int cnt = min(32, deg - base);
        for (int t = 0; t < cnt; t++) {
            float wt = __shfl_sync(0xffffffffu, w, t);
            int st = __shfl_sync(0xffffffffu, sv, t);
            acc0 = fmaf(wt, x[st * 64 + lane], acc0);
            acc1 = fmaf(wt, x[st * 64 + 32 + lane], acc1);
        }
    }
#pragma unroll
    for (int o = 16; o; o >>= 1) ws += __shfl_xor_sync(0xffffffffu, ws, o);
    float scale = 1.f / (ws + 1e-9f);
    g_agg[warp * 64 + lane] = acc0 * scale;
    g_agg[warp * 64 + 32 + lane] = acc1 * scale;
}

// ---------------- fused 2-layer update MLP ----------------
// out = relu(W2 @ relu(W1 @ [x|agg] + b1) + b2); 16 nodes per chunk
__global__ void update_kernel(const float* __restrict__ x,
                              const float* __restrict__ w1,
                              const float* __restrict__ b1,
                              const float* __restrict__ w2,
                              const float* __restrict__ b2,
                              float* __restrict__ out) {
    extern __shared__ float sm[];
    float* W1s = sm;                    // 128*129
    float* W2s = W1s + 128 * 129;       // 64*129
    float* Xs  = W2s + 64 * 129;        // 16*128
    float* Hs  = Xs + 16 * 128;         // 16*128
    float* b1s = Hs + 16 * 128;         // 128
    float* b2s = b1s + 128;             // 64
    int tid = threadIdx.x;

    for (int idx = tid; idx < 128 * 128; idx += 128) {
        int j = idx >> 7, f = idx & 127;
        W1s[j * 129 + f] = w1[idx];
    }
    for (int idx = tid; idx < 64 * 128; idx += 128) {
        int j = idx >> 7, f = idx & 127;
        W2s[j * 129 + f] = w2[idx];
    }
    if (tid < 128) b1s[tid] = b1[tid];
    if (tid < 64) b2s[tid] = b2[tid];
    __syncthreads();

    int nchunks = (N_NODES + 15) / 16;
    for (int c = blockIdx.x; c < nchunks; c += gridDim.x) {
        int n0 = c * 16;
        for (int idx = tid; idx < 16 * 128; idx += 128) {
            int n = idx >> 7, f = idx & 127;
            int node = n0 + n;
            float v = 0.f;
            if (node < N_NODES) v = (f < 64) ? x[node * 64 + f] : g_agg[node * 64 + (f - 64)];
            Xs[idx] = v;
        }
        __syncthreads();
        {   // stage 1: hidden layer, thread j computes h[j] for 16 nodes
            int j = tid;
            float acc[16];
#pragma unroll
            for (int n = 0; n < 16; n++) acc[n] = b1s[j];
            for (int f = 0; f < 128; f++) {
                float w = W1s[j * 129 + f];
#pragma unroll
                for (int n = 0; n < 16; n++) acc[n] = fmaf(w, Xs[n * 128 + f], acc[n]);
            }
#pragma unroll
            for (int n = 0; n < 16; n++) Hs[n * 128 + j] = fmaxf(acc[n], 0.f);
        }
        __syncthreads();
        {   // stage 2: output layer, thread (o, half) computes out[o] for 8 nodes
            int o = tid & 63, g = tid >> 6;
            float acc[8];
#pragma unroll
            for (int n = 0; n < 8; n++) acc[n] = b2s[o];
            for (int f = 0; f < 128; f++) {
                float w = W2s[o * 129 + f];
#pragma unroll
                for (int n = 0; n < 8; n++) acc[n] = fmaf(w, Hs[(g * 8 + n) * 128 + f], acc[n]);
            }
#pragma unroll
            for (int n = 0; n < 8; n++) {
                int node = n0 + g * 8 + n;
                if (node < N_NODES) out[node * 64 + o] = fmaxf(acc[n], 0.f);
            }
        }
        __syncthreads();
    }
}

// ---------------- launch ----------------
extern "C" void kernel_launch(void* const* d_in, const int* in_sizes, int n_in,
                              void* d_out, int out_size) {
    const float* x      = (const float*)d_in[0];
    const float* x_s    = (const float*)d_in[1];
    const int*   eidx   = (const int*)d_in[2];
    const float* efeat  = (const float*)d_in[3];
    const float* att_w1 = (const float*)d_in[4];
    const float* att_b1 = (const float*)d_in[5];
    const float* att_w2 = (const float*)d_in[6];
    const float* att_b2 = (const float*)d_in[7];
    const float* upd_w1 = (const float*)d_in[8];
    const float* upd_b1 = (const float*)d_in[9];
    const float* upd_w2 = (const float*)d_in[10];
    const float* upd_b2 = (const float*)d_in[11];
    float* out = (float*)d_out;

    const int PROJ_SMEM = (2 * 144 * 81 + 8 * 80) * (int)sizeof(float);      // ~95.9 KB
    const int UPD_SMEM  = (128 * 129 + 64 * 129 + 16 * 128 * 2 + 128 + 64) * (int)sizeof(float); // ~116.2 KB
    cudaFuncSetAttribute(proj_kernel, cudaFuncAttributeMaxDynamicSharedMemorySize, PROJ_SMEM);
    cudaFuncSetAttribute(update_kernel, cudaFuncAttributeMaxDynamicSharedMemorySize, UPD_SMEM);

    // CSR build
    zero_kernel<<<(N_NODES + 255) / 256, 256>>>();
    hist_kernel<<<(N_EDGES + 255) / 256, 256>>>(eidx);
    scan_kernel<<<1, 1024>>>();
    fill_kernel<<<(N_EDGES + 255) / 256, 256>>>(eidx);

    // node projections
    proj_kernel<<<296, 160, PROJ_SMEM>>>(x, x_s, att_w1);

    // edge attention scores
    edge_kernel<<<2048, 256>>>(eidx, efeat, att_w1, att_b1, att_w2, att_b2);

    // softmax + aggregation
    softagg_kernel<<<(N_NODES + 7) / 8, 256>>>(eidx, x);

    // update MLP
    update_kernel<<<148, 128, UPD_SMEM>>>(x, upd_w1, upd_b1, upd_w2, upd_b2, out);
}

// round 2
// speedup vs baseline: 1.6829x; 1.6829x over previous
#include <cuda_runtime.h>
#include <math.h>

#define N_NODES 50000
#define N_EDGES 800000
#define H 64
#define S 16
#define EF 16
#define ATT_W 144
#define UPD_W 128

// ---------------- scratch (static device allocations) ----------------
__device__ float g_Psrc[N_NODES * ATT_W];
__device__ float g_Pdst[N_NODES * ATT_W];
__device__ float g_raw[N_EDGES];            // CSR-ordered raw scores
__device__ float g_agg[N_NODES * H];
__device__ int   g_deg[N_NODES];
__device__ int   g_rowptr[N_NODES + 1];
__device__ int   g_cursor[N_NODES];
__device__ int   g_es[N_EDGES];             // CSR-ordered original edge id
__device__ int   g_ss[N_EDGES];             // CSR-ordered src
__device__ int   g_ds[N_EDGES];             // CSR-ordered dst

// ---------------- CSR build ----------------
__global__ void zero_kernel() {
    int i = blockIdx.x * blockDim.x + threadIdx.x;
    if (i < N_NODES) { g_deg[i] = 0; g_cursor[i] = 0; }
}

__global__ void hist_kernel(const int* __restrict__ ei) {
    int e = blockIdx.x * blockDim.x + threadIdx.x;
    if (e < N_EDGES) atomicAdd(&g_deg[ei[N_EDGES + e]], 1);
}

__global__ void scan_kernel() {
    __shared__ int sums[1024];
    const int CH = (N_NODES + 1023) / 1024;
    int t = threadIdx.x;
    int begin = t * CH;
    int end = min(begin + CH, N_NODES);
    int s = 0;
    for (int i = begin; i < end; i++) s += g_deg[i];
    sums[t] = s;
    __syncthreads();
    for (int off = 1; off < 1024; off <<= 1) {
        int v = (t >= off) ? sums[t - off] : 0;
        __syncthreads();
        sums[t] += v;
        __syncthreads();
    }
    int run = (t == 0) ? 0 : sums[t - 1];
    for (int i = begin; i < end; i++) { g_rowptr[i] = run; run += g_deg[i]; }
    if (t == 1023) g_rowptr[N_NODES] = sums[1023];
}

__global__ void fill_kernel(const int* __restrict__ ei) {
    int e = blockIdx.x * blockDim.x + threadIdx.x;
    if (e < N_EDGES) {
        int s = ei[e];
        int d = ei[N_EDGES + e];
        int pos = g_rowptr[d] + atomicAdd(&g_cursor[d], 1);
        g_es[pos] = e;
        g_ss[pos] = s;
        g_ds[pos] = d;
    }
}

// ---------------- node projections (register-tiled GEMM) ----------------
// Psrc/Pdst combined: 288 outputs x 80 inputs per node.
// 288 threads: tj = tid/8 (0..35, 8 j each), tn = tid%8 (2 nodes each), chunk = 16 nodes.
__global__ void proj_kernel(const float* __restrict__ x,
                            const float* __restrict__ xs,
                            const float* __restrict__ w1) {
    extern __shared__ float sm[];
    float* Wt = sm;                 // [f][j]: 80 x 288
    float* Xs = Wt + 80 * 288;      // [n][f]: 16 x 81 (pad)
    int tid = threadIdx.x;

    for (int idx = tid; idx < 80 * 288; idx += blockDim.x) {
        int j = idx % 288, f = idx / 288;
        int jr = (j < 144) ? j : j - 144;
        int col;
        if (j < 144) col = (f < 64) ? f : 64 + f;        // [0..64) | [128..144)
        else         col = (f < 64) ? 64 + f : 80 + f;   // [64..128) | [144..160)
        Wt[f * 288 + j] = w1[jr * 176 + col];
    }
    __syncthreads();

    int tj = tid >> 3;      // 0..35
    int tn = tid & 7;       // 0..7
    const int NCH = N_NODES / 16;   // 3125 exact

    for (int c = blockIdx.x; c < NCH; c += gridDim.x) {
        int n0 = c * 16;
        for (int idx = tid; idx < 16 * 80; idx += blockDim.x) {
            int n = idx / 80, f = idx % 80;
            int node = n0 + n;
            Xs[n * 81 + f] = (f < 64) ? x[node * 64 + f] : xs[node * 16 + (f - 64)];
        }
        __syncthreads();

        float acc[8][2];
#pragma unroll
        for (int jj = 0; jj < 8; jj++) { acc[jj][0] = 0.f; acc[jj][1] = 0.f; }

        for (int f = 0; f < 80; f++) {
            float4 w0 = *(const float4*)&Wt[f * 288 + tj * 8];
            float4 w1v = *(const float4*)&Wt[f * 288 + tj * 8 + 4];
            float x0 = Xs[(tn * 2 + 0) * 81 + f];
            float x1 = Xs[(tn * 2 + 1) * 81 + f];
            float wv[8] = {w0.x, w0.y, w0.z, w0.w, w1v.x, w1v.y, w1v.z, w1v.w};
#pragma unroll
            for (int jj = 0; jj < 8; jj++) {
                acc[jj][0] = fmaf(wv[jj], x0, acc[jj][0]);
                acc[jj][1] = fmaf(wv[jj], x1, acc[jj][1]);
            }
        }

#pragma unroll
        for (int u = 0; u < 2; u++) {
            int node = n0 + tn * 2 + u;
            float4 o0 = {acc[0][u], acc[1][u], acc[2][u], acc[3][u]};
            float4 o1 = {acc[4][u], acc[5][u], acc[6][u], acc[7][u]};
            int j = tj * 8;
            if (j < 144) {
                *(float4*)&g_Psrc[node * 144 + j] = o0;
                *(float4*)&g_Psrc[node * 144 + j + 4] = o1;
            } else {
                *(float4*)&g_Pdst[node * 144 + (j - 144)] = o0;
                *(float4*)&g_Pdst[node * 144 + (j - 144) + 4] = o1;
            }
        }
        __syncthreads();
    }
}

// ---------------- fused edge attention (weights in registers) ----------------
// warp per contiguous CSR range; Pdst cached in registers across same-d runs.
__global__ void __launch_bounds__(256, 2)
edge_kernel(const float* __restrict__ ef,
            const float* __restrict__ w1,
            const float* __restrict__ b1,
            const float* __restrict__ w2,
            const float* __restrict__ b2) {
    int tid = threadIdx.x;
    int lane = tid & 31;

    // hoist weights into registers (loop-invariant across edges)
    float wreg[16][5];
#pragma unroll
    for (int f = 0; f < 16; f++)
#pragma unroll
        for (int k = 0; k < 5; k++) {
            int j = lane + 32 * k;
            wreg[f][k] = (j < 144) ? w1[j * 176 + 160 + f] : 0.f;
        }
    float b1r[5], w2r[5];
#pragma unroll
    for (int k = 0; k < 5; k++) {
        int j = lane + 32 * k;
        b1r[k] = (j < 144) ? b1[j] : 0.f;
        w2r[k] = (j < 144) ? w2[j] : 0.f;
    }
    float b2v = b2[0];

    int gw = (blockIdx.x * blockDim.x + tid) >> 5;
    int nw = (gridDim.x * blockDim.x) >> 5;
    int chunk = (N_EDGES + nw - 1) / nw;
    int p0 = gw * chunk;
    int p1 = min(p0 + chunk, N_EDGES);

    int dcur = -1;
    float pd[5] = {0.f, 0.f, 0.f, 0.f, 0.f};

    for (int p = p0; p < p1; p++) {
        int s = g_ss[p];
        int d = g_ds[p];
        int e = g_es[p];
        float efv = (lane < 16) ? ef[e * 16 + lane] : 0.f;

        if (d != dcur) {
            dcur = d;
#pragma unroll
            for (int k = 0; k < 5; k++) {
                int j = lane + 32 * k;
                pd[k] = (j < 144) ? b1r[k] + g_Pdst[d * 144 + j] : 0.f;
            }
        }

        float acc[5];
#pragma unroll
        for (int k = 0; k < 5; k++) {
            int j = lane + 32 * k;
            acc[k] = (j < 144) ? pd[k] + g_Psrc[s * 144 + j] : 0.f;
        }

#pragma unroll
        for (int f = 0; f < 16; f++) {
            float v = __shfl_sync(0xffffffffu, efv, f);
#pragma unroll
            for (int k = 0; k < 5; k++)
                acc[k] = fmaf(v, wreg[f][k], acc[k]);
        }

        float pr = 0.f;
#pragma unroll
        for (int k = 0; k < 5; k++)
            pr = fmaf(fmaxf(acc[k], 0.f), w2r[k], pr);
#pragma unroll
        for (int o = 16; o; o >>= 1) pr += __shfl_xor_sync(0xffffffffu, pr, o);

        if (lane == 0) {
            float r = pr + b2v;
            g_raw[p] = (r > 0.f) ? r : 0.01f * r;
        }
    }
}

// ---------------- fused segment softmax + weighted aggregation ----------------
// warp per destination node; all g_raw / g_ss reads contiguous.
__global__ void softagg_kernel(const float* __restrict__ x) {
    int warp = (blockIdx.x * blockDim.x + threadIdx.x) >> 5;
    int lane = threadIdx.x & 31;
    if (warp >= N_NODES) return;
    int start = g_rowptr[warp];
    int deg = g_rowptr[warp + 1] - start;

    float m = -1e30f;
    for (int i = lane; i < deg; i += 32) m = fmaxf(m, g_raw[start + i]);
#pragma unroll
    for (int o = 16; o; o >>= 1) m = fmaxf(m, __shfl_xor_sync(0xffffffffu, m, o));

    float acc0 = 0.f, acc1 = 0.f, ws = 0.f;
    for (int base = 0; base < deg; base += 32) {
        int i = base + lane;
        float w = (i < deg) ? __expf(g_raw[start + i] - m) : 0.f;
        int sv = (i < deg) ? g_ss[start + i] : 0;
        ws += w;
        int cnt = min(32, deg - base);
        for (int t = 0; t < cnt; t++) {
            float wt = __shfl_sync(0xffffffffu, w, t);
            int st = __shfl_sync(0xffffffffu, sv, t);
            acc0 = fmaf(wt, x[st * 64 + lane], acc0);
            acc1 = fmaf(wt, x[st * 64 + 32 + lane], acc1);
        }
    }
#pragma unroll
    for (int o = 16; o; o >>= 1) ws += __shfl_xor_sync(0xffffffffu, ws, o);
    float scale = 1.f / (ws + 1e-9f);
    g_agg[warp * 64 + lane] = acc0 * scale;
    g_agg[warp * 64 + 32 + lane] = acc1 * scale;
}

// ---------------- fused 2-layer update MLP (register-tiled) ----------------
// 256 threads, chunk = 64 nodes.
// stage1: thread (tj,tn): 8 j x 4 n.  stage2: thread (to,tn): 4 o x 4 n.
__global__ void update_kernel(const float* __restrict__ x,
                              const float* __restrict__ w1,
                              const float* __restrict__ b1,
                              const float* __restrict__ w2,
                              const float* __restrict__ b2,
                              float* __restrict__ out) {
    extern __shared__ float sm[];
    float* W1t = sm;                    // [f][j]: 128 x 128
    float* W2t = W1t + 128 * 128;       // [j][o]: 128 x 64
    float* Xs  = W2t + 128 * 64;        // [n][f]: 64 x 129
    float* Hs  = Xs + 64 * 129;         // [j][n]: 128 x 68
    float* b1s = Hs + 128 * 68;         // 128
    float* b2s = b1s + 128;             // 64
    int tid = threadIdx.x;

    for (int idx = tid; idx < 128 * 128; idx += 256) {
        int j = idx >> 7, f = idx & 127;
        W1t[f * 128 + j] = w1[idx];
    }
    for (int idx = tid; idx < 64 * 128; idx += 256) {
        int o = idx >> 7, j = idx & 127;
        W2t[j * 64 + o] = w2[idx];
    }
    if (tid < 128) b1s[tid] = b1[tid];
    if (tid < 64) b2s[tid] = b2[tid];
    __syncthreads();

    int tn = tid & 15;      // 0..15
    int tj = tid >> 4;      // 0..15 (stage1: 8 j each) / stage2 reuse as to-group
    const int NCH = (N_NODES + 63) / 64;    // 782

    for (int c = blockIdx.x; c < NCH; c += gridDim.x) {
        int n0 = c * 64;
        for (int idx = tid; idx < 64 * 128; idx += 256) {
            int n = idx >> 7, f = idx & 127;
            int node = n0 + n;
            float v = 0.f;
            if (node < N_NODES)
                v = (f < 64) ? x[node * 64 + f] : g_agg[node * 64 + (f - 64)];
            Xs[n * 129 + f] = v;
        }
        __syncthreads();

        // stage 1: H[j][n] = relu(W1 @ X + b1)
        {
            float acc[8][4];
#pragma unroll
            for (int jj = 0; jj < 8; jj++)
#pragma unroll
                for (int nn = 0; nn < 4; nn++) acc[jj][nn] = 0.f;

            for (int f = 0; f < 128; f++) {
                float4 w0 = *(const float4*)&W1t[f * 128 + tj * 8];
                float4 w1v = *(const float4*)&W1t[f * 128 + tj * 8 + 4];
                float wv[8] = {w0.x, w0.y, w0.z, w0.w, w1v.x, w1v.y, w1v.z, w1v.w};
                float xv[4];
#pragma unroll
                for (int nn = 0; nn < 4; nn++) xv[nn] = Xs[(tn * 4 + nn) * 129 + f];
#pragma unroll
                for (int jj = 0; jj < 8; jj++)
#pragma unroll
                    for (int nn = 0; nn < 4; nn++)
                        acc[jj][nn] = fmaf(wv[jj], xv[nn], acc[jj][nn]);
            }
#pragma unroll
            for (int jj = 0; jj < 8; jj++) {
                float b = b1s[tj * 8 + jj];
                float4 hv = {fmaxf(acc[jj][0] + b, 0.f), fmaxf(acc[jj][1] + b, 0.f),
                             fmaxf(acc[jj][2] + b, 0.f), fmaxf(acc[jj][3] + b, 0.f)};
                *(float4*)&Hs[(tj * 8 + jj) * 68 + tn * 4] = hv;
            }
        }
        __syncthreads();

        // stage 2: out[o][n] = relu(W2 @ H + b2)
        {
            int to = tid & 15;      // 4 o each
            int tn2 = tid >> 4;     // 4 n each
            float acc2[4][4];       // [nn][oo]
#pragma unroll
            for (int nn = 0; nn < 4; nn++)
#pragma unroll
                for (int oo = 0; oo < 4; oo++) acc2[nn][oo] = 0.f;

            for (int j = 0; j < 128; j++) {
                float4 wv = *(const float4*)&W2t[j * 64 + to * 4];
                float4 hv = *(const float4*)&Hs[j * 68 + tn2 * 4];
                float h[4] = {hv.x, hv.y, hv.z, hv.w};
                float w[4] = {wv.x, wv.y, wv.z, wv.w};
#pragma unroll
                for (int nn = 0; nn < 4; nn++)
#pragma unroll
                    for (int oo = 0; oo < 4; oo++)
                        acc2[nn][oo] = fmaf(w[oo], h[nn], acc2[nn][oo]);
            }
#pragma unroll
            for (int nn = 0; nn < 4; nn++) {
                int node = n0 + tn2 * 4 + nn;
                if (node < N_NODES) {
                    float4 ov = {fmaxf(acc2[nn][0] + b2s[to * 4 + 0], 0.f),
                                 fmaxf(acc2[nn][1] + b2s[to * 4 + 1], 0.f),
                                 fmaxf(acc2[nn][2] + b2s[to * 4 + 2], 0.f),
                                 fmaxf(acc2[nn][3] + b2s[to * 4 + 3], 0.f)};
                    *(float4*)&out[node * 64 + to * 4] = ov;
                }
            }
        }
        __syncthreads();
    }
}

// ---------------- launch ----------------
extern "C" void kernel_launch(void* const* d_in, const int* in_sizes, int n_in,
                              void* d_out, int out_size) {
    const float* x      = (const float*)d_in[0];
    const float* x_s    = (const float*)d_in[1];
    const int*   eidx   = (const int*)d_in[2];
    const float* efeat  = (const float*)d_in[3];
    const float* att_w1 = (const float*)d_in[4];
    const float* att_b1 = (const float*)d_in[5];
    const float* att_w2 = (const float*)d_in[6];
    const float* att_b2 = (const float*)d_in[7];
    const float* upd_w1 = (const float*)d_in[8];
    const float* upd_b1 = (const float*)d_in[9];
    const float* upd_w2 = (const float*)d_in[10];
    const float* upd_b2 = (const float*)d_in[11];
    float* out = (float*)d_out;

    const int PROJ_SMEM = (80 * 288 + 16 * 81) * (int)sizeof(float);                         // ~95.1 KB
    const int UPD_SMEM  = (128 * 128 + 128 * 64 + 64 * 129 + 128 * 68 + 128 + 64) * (int)sizeof(float); // ~163 KB
    cudaFuncSetAttribute(proj_kernel, cudaFuncAttributeMaxDynamicSharedMemorySize, PROJ_SMEM);
    cudaFuncSetAttribute(update_kernel, cudaFuncAttributeMaxDynamicSharedMemorySize, UPD_SMEM);

    // CSR build
    zero_kernel<<<(N_NODES + 255) / 256, 256>>>();
    hist_kernel<<<(N_EDGES + 255) / 256, 256>>>(eidx);
    scan_kernel<<<1, 1024>>>();
    fill_kernel<<<(N_EDGES + 255) / 256, 256>>>(eidx);

    // node projections
    proj_kernel<<<296, 288, PROJ_SMEM>>>(x, x_s, att_w1);

    // edge attention scores (CSR order)
    edge_kernel<<<296, 256>>>(efeat, att_w1, att_b1, att_w2, att_b2);

    // softmax + aggregation
    softagg_kernel<<<(N_NODES * 32 + 255) / 256, 256>>>(x);

    // update MLP
    update_kernel<<<148, 256, UPD_SMEM>>>(x, upd_w1, upd_b1, upd_w2, upd_b2, out);
}